// round 5
// baseline (speedup 1.0000x reference)
#include <cuda_runtime.h>
#include <cstdint>
#include <cstddef>

#define LOG2E_F 1.4426950408889634f
#define LN2_F   0.6931471805599453f

__device__ __forceinline__ float ex2f_(float x) {
    float y; asm("ex2.approx.ftz.f32 %0, %1;" : "=f"(y) : "f"(x)); return y;
}
__device__ __forceinline__ float lg2f_(float x) {
    float y; asm("lg2.approx.f32 %0, %1;" : "=f"(y) : "f"(x)); return y;
}
__device__ __forceinline__ unsigned long long pk2(float lo, float hi) {
    unsigned long long r; asm("mov.b64 %0, {%1, %2};" : "=l"(r) : "f"(lo), "f"(hi)); return r;
}
__device__ __forceinline__ void upk2(unsigned long long v, float& lo, float& hi) {
    asm("mov.b64 {%0, %1}, %2;" : "=f"(lo), "=f"(hi) : "l"(v));
}
__device__ __forceinline__ void fma2_(unsigned long long& acc, unsigned long long a, unsigned long long b) {
    asm("fma.rn.f32x2 %0, %1, %2, %0;" : "+l"(acc) : "l"(a), "l"(b));
}
__device__ __forceinline__ unsigned long long add2_(unsigned long long a, unsigned long long b) {
    unsigned long long r; asm("add.rn.f32x2 %0, %1, %2;" : "=l"(r) : "l"(a), "l"(b)); return r;
}

// One CTA per batch, 128 threads, thread j owns output column j:
// it computes the FULL 128-i dot product w_j = sum_i v_i * E[i][j] alone.
// -> NO butterfly shuffles and no cross-thread combine on the per-step
// critical path (the R3/R4 bottleneck). E[:, j] lives in registers as 64
// i-pair-packed f32x2 operands; v is broadcast from smem via 64 conflict-free
// LDS.64 feeding 8 independent fma.rn.f32x2 chains. Forward vector kept
// linear-domain; exact power-of-2 renorm every 8 steps (warp REDUX + 4-way
// smem max published at t%8==0, folded at t%8==1). One __syncthreads (4
// warps) per step. obs streamed via an 8-deep register prefetch ring
// (coalesced 32-bit loads, 512B per CTA-step).
__global__ __launch_bounds__(128, 1)
void crf_fwd_kernel(const float* __restrict__ obs,
                    const float* __restrict__ logA,
                    float* __restrict__ out,
                    int T)
{
    constexpr int S = 128;
    __shared__ __align__(16) float v_sm[2][S];
    __shared__ float wm[4];
    __shared__ float wsum[4];

    const int tid  = threadIdx.x;     // == column j
    const int b    = blockIdx.x;
    const int warp = tid >> 5;

    const float* ob = obs + (size_t)b * (size_t)T * S + tid;

    // A[k] = {E[2k][j], E[2k+1][j]}  (column j of exp(logA), i-pair packed)
    unsigned long long A[64];
#pragma unroll
    for (int k = 0; k < 64; ++k) {
        const float ea = logA[(size_t)(2 * k) * S + tid];
        const float eb = logA[(size_t)(2 * k + 1) * S + tid];
        A[k] = pk2(ex2f_(ea * LOG2E_F), ex2f_(eb * LOG2E_F));
    }

    // ---- t = 0 (t%8==0): u = exp(obs[0]) raw; publish block max ----
    const float o0 = ob[0];
    const float u  = ex2f_(o0 * LOG2E_F);
    {
        const int im = __reduce_max_sync(0xffffffffu, __float_as_int(u));
        if ((tid & 31) == 0) wm[warp] = __int_as_float(im);
        v_sm[0][tid] = u;
    }

    // 8-deep obs prefetch ring: oR[t & 7] holds obs[t].
    float oR[8];
#pragma unroll
    for (int k = 1; k <= 8; ++k)
        oR[k & 7] = (k < T) ? __ldcs(ob + (size_t)k * S) : o0;

    int L = 0;                 // exact accumulated log2 scale (uniform across block)
    __syncthreads();

    // ---- scan t = 1 .. T-1, ONE barrier per step ----
#pragma unroll 2
    for (int t = 1; t < T; ++t) {
        const int cb = (t - 1) & 1, nb = t & 1;

        const float oc = oR[t & 7];
        if (t + 8 < T) oR[t & 7] = __ldcs(ob + (size_t)(t + 8) * S);

        // observation factor early (MUFU latency hides under the matvec)
        const float p = ex2f_(oc * LOG2E_F);

        // fold previous publish's exact 2^-e every 8th step
        float sc = 1.0f;
        const bool fold = (t & 7) == 1;
        if (fold) {
            const float m = fmaxf(fmaxf(wm[0], wm[1]), fmaxf(wm[2], wm[3]));
            const int e = ((__float_as_int(m) >> 23) & 0xFF) - 127;
            L += e;
            sc = __int_as_float((127 - e) << 23);   // exact 2^-e
        }

        // full 128-i dot product: 64 broadcast LDS.64, 8 independent fma2 chains
        const unsigned long long* V =
            reinterpret_cast<const unsigned long long*>(&v_sm[cb][0]);
        unsigned long long c0 = 0ull, c1 = 0ull, c2 = 0ull, c3 = 0ull;
        unsigned long long c4 = 0ull, c5 = 0ull, c6 = 0ull, c7 = 0ull;
#pragma unroll
        for (int k = 0; k < 8; ++k) {
            fma2_(c0, V[8 * k + 0], A[8 * k + 0]);
            fma2_(c1, V[8 * k + 1], A[8 * k + 1]);
            fma2_(c2, V[8 * k + 2], A[8 * k + 2]);
            fma2_(c3, V[8 * k + 3], A[8 * k + 3]);
            fma2_(c4, V[8 * k + 4], A[8 * k + 4]);
            fma2_(c5, V[8 * k + 5], A[8 * k + 5]);
            fma2_(c6, V[8 * k + 6], A[8 * k + 6]);
            fma2_(c7, V[8 * k + 7], A[8 * k + 7]);
        }
        const unsigned long long s01 = add2_(c0, c1);
        const unsigned long long s23 = add2_(c2, c3);
        const unsigned long long s45 = add2_(c4, c5);
        const unsigned long long s67 = add2_(c6, c7);
        const unsigned long long sA  = add2_(s01, s23);
        const unsigned long long sB  = add2_(s45, s67);
        float lo, hi;
        upk2(add2_(sA, sB), lo, hi);
        const float acc = lo + hi;

        const float un = fold ? acc * (p * sc) : acc * p;

        // publish block max every 8th step (consumed at t+1)
        if ((t & 7) == 0) {
            const int im = __reduce_max_sync(0xffffffffu, __float_as_int(un));
            if ((tid & 31) == 0) wm[warp] = __int_as_float(im);
        }
        v_sm[nb][tid] = un;
        __syncthreads();
    }

    // ---- finalize: out[b] = -ln2 * (log2(sum_j v_j) + L) ----
    const int fb = (T - 1) & 1;
    float vv = v_sm[fb][tid];
#pragma unroll
    for (int o = 16; o; o >>= 1) vv += __shfl_xor_sync(0xffffffffu, vv, o);
    if ((tid & 31) == 0) wsum[warp] = vv;
    __syncthreads();
    if (tid == 0) {
        const float s = (wsum[0] + wsum[1]) + (wsum[2] + wsum[3]);
        out[b] = -LN2_F * (lg2f_(s) + (float)L);
    }
}

extern "C" void kernel_launch(void* const* d_in, const int* in_sizes, int n_in,
                              void* d_out, int out_size)
{
    const float* obs  = (const float*)d_in[0];   // [B, T, S] f32
    const float* logA = (const float*)d_in[1];   // [S, S]   f32
    float* out = (float*)d_out;                  // [B]      f32

    const int B = out_size;
    const int S = 128;
    const int T = in_sizes[0] / (B * S);

    crf_fwd_kernel<<<B, 128>>>(obs, logA, out, T);
}